// round 3
// baseline (speedup 1.0000x reference)
#include <cuda_runtime.h>
#include <cuda_fp16.h>
#include <math.h>

#define NMAX 50048
#define EMAX 800032
#define SLOPE 0.2f

// ---- scratch (no allocs allowed) ----
__device__ float  g_h[(size_t)NMAX * 128];   // transformed features (fp32)
__device__ __half g_hh[(size_t)NMAX * 128];  // transformed features (fp16 copy)
__device__ float  g_as[NMAX];                // src logits
__device__ float  g_ad[NMAX];                // dst logits
__device__ int    g_deg[NMAX];               // in-degree histogram
__device__ int    g_scan[NMAX];              // block-local exclusive scan
__device__ int    g_bt[256];                 // per-block totals
__device__ int    g_off[NMAX + 1];           // CSR offsets
__device__ int    g_cur[NMAX];               // fill cursors
__device__ int    g_eidx[EMAX];              // CSR: src index per slot
__device__ int    g_is64;

// ============================================================
// helpers: tf32 split + mma
// ============================================================
__device__ __forceinline__ void split_tf32(float x, unsigned& hi, unsigned& lo) {
    unsigned h;
    asm("cvt.rna.tf32.f32 %0, %1;" : "=r"(h) : "f"(x));
    float hf = __uint_as_float(h);
    float l = x - hf;
    unsigned lr;
    asm("cvt.rna.tf32.f32 %0, %1;" : "=r"(lr) : "f"(l));
    hi = h; lo = lr;
}

__device__ __forceinline__ void mma_tf32(float* c, const unsigned* a, const unsigned* b) {
    asm volatile(
        "mma.sync.aligned.m16n8k8.row.col.f32.tf32.tf32.f32 "
        "{%0,%1,%2,%3},{%4,%5,%6,%7},{%8,%9},{%0,%1,%2,%3};"
        : "+f"(c[0]), "+f"(c[1]), "+f"(c[2]), "+f"(c[3])
        : "r"(a[0]), "r"(a[1]), "r"(a[2]), "r"(a[3]), "r"(b[0]), "r"(b[1]));
}

// ============================================================
// K0: detect whether edge_index buffer is int64 or int32
// ============================================================
__global__ void detect_kernel(const long long* __restrict__ ei, int E, int N) {
    __shared__ int bad;
    if (threadIdx.x == 0) bad = 0;
    __syncthreads();
    int i = threadIdx.x;
    if (i < E) {
        long long v = ei[i];
        if (v < 0 || v >= (long long)N) atomicOr(&bad, 1);
    }
    __syncthreads();
    if (threadIdx.x == 0) g_is64 = bad ? 0 : 1;
}

// ============================================================
// K1: h = x @ W  via 3xTF32 tensor-core MMA (fp32-equivalent)
// block: 128 rows x 128 cols, 8 warps (4m x 2n), warp = 32x64
// ============================================================
__global__ __launch_bounds__(256)
void gemm_tf32(const float* __restrict__ x, const float* __restrict__ W, int N) {
    __shared__ float xs[128][36];   // [row][k], pad 36 -> conflict-free A frags
    __shared__ float ws[32][136];   // [k][col], pad 136 -> conflict-free B frags

    int tid = threadIdx.x;
    int warp = tid >> 5, lane = tid & 31;
    int warpM = warp >> 1;          // 0..3
    int warpN = warp & 1;           // 0..1
    int g = lane >> 2, tg = lane & 3;
    int rowBase = blockIdx.x * 128;

    float acc[2][8][4];
#pragma unroll
    for (int mt = 0; mt < 2; mt++)
#pragma unroll
        for (int nt = 0; nt < 8; nt++)
#pragma unroll
            for (int q = 0; q < 4; q++) acc[mt][nt][q] = 0.f;

    for (int kc = 0; kc < 128; kc += 32) {
        // stage x tile: 128 rows x 32 k (1024 float4, 4 per thread)
#pragma unroll
        for (int it = 0; it < 4; it++) {
            int v = tid + it * 256;
            int r = v >> 3;
            int kq = v & 7;
            int gr = rowBase + r;
            float4 xv = make_float4(0.f, 0.f, 0.f, 0.f);
            if (gr < N) xv = *(const float4*)&x[(size_t)gr * 128 + kc + kq * 4];
            *(float4*)&xs[r][kq * 4] = xv;
        }
        // stage W chunk: 32 k x 128 cols
#pragma unroll
        for (int it = 0; it < 4; it++) {
            int v = tid + it * 256;
            int k = v >> 5;
            int nq = v & 31;
            float4 wv = *(const float4*)&W[(size_t)(kc + k) * 128 + nq * 4];
            *(float4*)&ws[k][nq * 4] = wv;
        }
        __syncthreads();

#pragma unroll
        for (int ks = 0; ks < 4; ks++) {
            int kb = ks * 8;
            unsigned ahi[2][4], alo[2][4];
#pragma unroll
            for (int mt = 0; mt < 2; mt++) {
                int r0 = warpM * 32 + mt * 16;
                float a0 = xs[r0 + g][kb + tg];
                float a1 = xs[r0 + g + 8][kb + tg];
                float a2 = xs[r0 + g][kb + tg + 4];
                float a3 = xs[r0 + g + 8][kb + tg + 4];
                split_tf32(a0, ahi[mt][0], alo[mt][0]);
                split_tf32(a1, ahi[mt][1], alo[mt][1]);
                split_tf32(a2, ahi[mt][2], alo[mt][2]);
                split_tf32(a3, ahi[mt][3], alo[mt][3]);
            }
#pragma unroll
            for (int nt = 0; nt < 8; nt++) {
                int c0 = warpN * 64 + nt * 8 + g;
                float b0 = ws[kb + tg][c0];
                float b1 = ws[kb + tg + 4][c0];
                unsigned bhi[2], blo[2];
                split_tf32(b0, bhi[0], blo[0]);
                split_tf32(b1, bhi[1], blo[1]);
#pragma unroll
                for (int mt = 0; mt < 2; mt++) {
                    mma_tf32(acc[mt][nt], ahi[mt], bhi);
                    mma_tf32(acc[mt][nt], ahi[mt], blo);
                    mma_tf32(acc[mt][nt], alo[mt], bhi);
                }
            }
        }
        __syncthreads();
    }

    // epilogue: write fp32 + fp16 copies
#pragma unroll
    for (int mt = 0; mt < 2; mt++) {
#pragma unroll
        for (int nt = 0; nt < 8; nt++) {
            int row0 = rowBase + warpM * 32 + mt * 16 + g;
            int col0 = warpN * 64 + nt * 8 + tg * 2;
            if (row0 < N) {
                *(float2*)&g_h[(size_t)row0 * 128 + col0] =
                    make_float2(acc[mt][nt][0], acc[mt][nt][1]);
                *(__half2*)&g_hh[(size_t)row0 * 128 + col0] =
                    __floats2half2_rn(acc[mt][nt][0], acc[mt][nt][1]);
            }
            int row1 = row0 + 8;
            if (row1 < N) {
                *(float2*)&g_h[(size_t)row1 * 128 + col0] =
                    make_float2(acc[mt][nt][2], acc[mt][nt][3]);
                *(__half2*)&g_hh[(size_t)row1 * 128 + col0] =
                    __floats2half2_rn(acc[mt][nt][2], acc[mt][nt][3]);
            }
        }
    }
}

// ============================================================
// K2: per-node logits a_s, a_d (warp per node); zero histogram
// ============================================================
__global__ void node_logits(const float* __restrict__ att_s,
                            const float* __restrict__ att_d, int N) {
    int warp = (blockIdx.x * blockDim.x + threadIdx.x) >> 5;
    int lane = threadIdx.x & 31;
    if (warp >= N) return;
    float4 hv = *(const float4*)&g_h[(size_t)warp * 128 + lane * 4];
    float4 s4 = *(const float4*)&att_s[lane * 4];
    float4 d4 = *(const float4*)&att_d[lane * 4];
    float s = hv.x * s4.x + hv.y * s4.y + hv.z * s4.z + hv.w * s4.w;
    float d = hv.x * d4.x + hv.y * d4.y + hv.z * d4.z + hv.w * d4.w;
#pragma unroll
    for (int o = 16; o > 0; o >>= 1) {
        s += __shfl_xor_sync(0xffffffffu, s, o);
        d += __shfl_xor_sync(0xffffffffu, d, o);
    }
    if (lane == 0) {
        g_as[warp] = s;
        g_ad[warp] = d;
        g_deg[warp] = 0;
    }
}

// ============================================================
// K3: in-degree histogram over dst (4 edges/thread for MLP)
// ============================================================
__global__ void hist_kernel(const long long* __restrict__ ei, int E) {
    int base = (blockIdx.x * blockDim.x + threadIdx.x) * 4;
    if (base >= E) return;
    int n = E - base; if (n > 4) n = 4;
    int d[4];
    if (g_is64) {
#pragma unroll
        for (int j = 0; j < 4; j++)
            if (j < n) d[j] = (int)ei[(size_t)E + base + j];
    } else {
        const int* p32 = (const int*)ei;
#pragma unroll
        for (int j = 0; j < 4; j++)
            if (j < n) d[j] = p32[E + base + j];
    }
#pragma unroll
    for (int j = 0; j < 4; j++)
        if (j < n) atomicAdd(&g_deg[d[j]], 1);
}

// ============================================================
// K4a: block-local exclusive scan (256 per block) + block totals
// ============================================================
__global__ void scan_blocks(int N) {
    __shared__ int sh[256];
    int i = blockIdx.x * 256 + threadIdx.x;
    int v = (i < N) ? g_deg[i] : 0;
    sh[threadIdx.x] = v;
    __syncthreads();
#pragma unroll
    for (int o = 1; o < 256; o <<= 1) {
        int t = (threadIdx.x >= o) ? sh[threadIdx.x - o] : 0;
        __syncthreads();
        sh[threadIdx.x] += t;
        __syncthreads();
    }
    if (i < N) g_scan[i] = sh[threadIdx.x] - v;  // exclusive
    if (threadIdx.x == 255) g_bt[blockIdx.x] = sh[255];
}

// ============================================================
// K4b: scan the block totals (single block), set g_off[N]=E
// ============================================================
__global__ void scan_totals(int nb, int E, int N) {
    __shared__ int sh[256];
    int v = (threadIdx.x < nb) ? g_bt[threadIdx.x] : 0;
    sh[threadIdx.x] = v;
    __syncthreads();
#pragma unroll
    for (int o = 1; o < 256; o <<= 1) {
        int t = (threadIdx.x >= o) ? sh[threadIdx.x - o] : 0;
        __syncthreads();
        sh[threadIdx.x] += t;
        __syncthreads();
    }
    g_bt[threadIdx.x] = sh[threadIdx.x] - v;  // exclusive totals
    if (threadIdx.x == 0) g_off[N] = E;
}

// ============================================================
// K4c: add back -> CSR offsets + cursors
// ============================================================
__global__ void scan_addback(int N) {
    int i = blockIdx.x * 256 + threadIdx.x;
    if (i >= N) return;
    int o = g_scan[i] + g_bt[blockIdx.x];
    g_off[i] = o;
    g_cur[i] = o;
}

// ============================================================
// K5: fill CSR slots with src indices (4 edges/thread)
// ============================================================
__global__ void fill_kernel(const long long* __restrict__ ei, int E) {
    int base = (blockIdx.x * blockDim.x + threadIdx.x) * 4;
    if (base >= E) return;
    int n = E - base; if (n > 4) n = 4;
    int s[4], d[4];
    if (g_is64) {
#pragma unroll
        for (int j = 0; j < 4; j++)
            if (j < n) {
                s[j] = (int)ei[base + j];
                d[j] = (int)ei[(size_t)E + base + j];
            }
    } else {
        const int* p32 = (const int*)ei;
#pragma unroll
        for (int j = 0; j < 4; j++)
            if (j < n) {
                s[j] = p32[base + j];
                d[j] = p32[E + base + j];
            }
    }
#pragma unroll
    for (int j = 0; j < 4; j++)
        if (j < n) {
            int slot = atomicAdd(&g_cur[d[j]], 1);
            g_eidx[slot] = s[j];
        }
}

// ============================================================
// K6: fused softmax + aggregate (warp per dst, fp16 gathers)
// ============================================================
__global__ __launch_bounds__(256)
void aggregate(float* __restrict__ out, const float* __restrict__ bias, int N) {
    int node = (blockIdx.x * blockDim.x + threadIdx.x) >> 5;
    int lane = threadIdx.x & 31;
    if (node >= N) return;

    float ad = g_ad[node];
    float e0 = g_as[node] + ad;
    e0 = e0 > 0.f ? e0 : SLOPE * e0;
    float pself = expf(e0);

    // self contribution (fp16 path, same as edges)
    const __half2* hp0 = (const __half2*)&g_hh[(size_t)node * 128 + lane * 4];
    float2 f0 = __half22float2(hp0[0]);
    float2 f1 = __half22float2(hp0[1]);
    float4 acc;
    acc.x = pself * f0.x;
    acc.y = pself * f0.y;
    acc.z = pself * f1.x;
    acc.w = pself * f1.y;
    float den = pself;

    int beg = g_off[node];
    int end = g_off[node + 1];
    for (int base = beg; base < end; base += 32) {
        int e = base + lane;
        int s = (e < end) ? g_eidx[e] : 0;
        int nv = end - base;
        if (nv > 32) nv = 32;
#pragma unroll 4
        for (int j = 0; j < nv; j++) {
            int sj = __shfl_sync(0xffffffffu, s, j);
            float v = g_as[sj] + ad;
            v = v > 0.f ? v : SLOPE * v;
            float p = expf(v);
            const __half2* hp = (const __half2*)&g_hh[(size_t)sj * 128 + lane * 4];
            float2 a0 = __half22float2(hp[0]);
            float2 a1 = __half22float2(hp[1]);
            den += p;
            acc.x += p * a0.x;
            acc.y += p * a0.y;
            acc.z += p * a1.x;
            acc.w += p * a1.y;
        }
    }

    float inv = 1.f / den;
    float4 b = *(const float4*)&bias[lane * 4];
    float4 o;
    o.x = acc.x * inv + b.x;
    o.y = acc.y * inv + b.y;
    o.z = acc.z * inv + b.z;
    o.w = acc.w * inv + b.w;
    *(float4*)&out[(size_t)node * 128 + lane * 4] = o;
}

// ============================================================
extern "C" void kernel_launch(void* const* d_in, const int* in_sizes, int n_in,
                              void* d_out, int out_size) {
    const float*     x     = (const float*)d_in[0];
    const long long* ei    = (const long long*)d_in[1];
    const float*     W     = (const float*)d_in[2];
    const float*     att_s = (const float*)d_in[3];
    const float*     att_d = (const float*)d_in[4];
    const float*     bias  = (const float*)d_in[5];
    float*           out   = (float*)d_out;

    int N = in_sizes[0] / 128;
    int E = in_sizes[1] / 2;
    int nb = (N + 255) / 256;
    int e4blocks = ((E + 3) / 4 + 255) / 256;

    detect_kernel<<<1, 1024>>>(ei, E, N);
    gemm_tf32<<<(N + 127) / 128, 256>>>(x, W, N);
    node_logits<<<(N + 7) / 8, 256>>>(att_s, att_d, N);
    hist_kernel<<<e4blocks, 256>>>(ei, E);
    scan_blocks<<<nb, 256>>>(N);
    scan_totals<<<1, 256>>>(nb, E, N);
    scan_addback<<<nb, 256>>>(N);
    fill_kernel<<<e4blocks, 256>>>(ei, E);
    aggregate<<<(N * 32 + 255) / 256, 256>>>(out, bias, N);
}